// round 12
// baseline (speedup 1.0000x reference)
#include <cuda_runtime.h>
#include <cuda_fp16.h>
#include <cstdint>

#define B2   8192
#define D    512
#define KD   2048      // fp16 cols: [0,1024) hi, [1024,2048) lo
#define NM1  8191

#define TM   256
#define TN   128
#define BK   128       // fp16 per chunk (256 B rows)
#define NSTG 2
#define NCH  24        // 16 cross (K=2048, fp16 acc) + 8 hihi (K=1024, fp32 acc)

#define ROWB 272                       // 256 B data + 16 B pad
#define A_SZ (256 * ROWB)              // 69632
#define B_SZ (128 * ROWB)              // 34816
#define STAGE_SZ (A_SZ + B_SZ)         // 104448
#define SM_TOTAL (NSTG * STAGE_SZ)     // 208896

// ---------------- device scratch ----------------
__device__ __align__(128) __half g_Ah[(size_t)B2 * KD];  // [hi(x^2)|hi(x)|lo(x^2)|lo(x)]
__device__ __align__(128) __half g_Bh[(size_t)B2 * KD];  // [hi(1/s)|hi(-2x/s)|lo(1/s)|lo(-2x/s)]
__device__ float g_t3[B2];
__device__ float g_ls[B2];
__device__ float g_c[B2];      // 0.1*gt_i + 0.5*ls_i
__device__ float g_cj[B2];     // -0.5*ls[pos(j)] - 0.1*t3[j]
__device__ float g_rowsum[B2];

// ---------------- PTX helpers ----------------
__device__ __forceinline__ uint32_t smem_u32(const void* p) {
    uint32_t a;
    asm("{ .reg .u64 t; cvta.to.shared.u64 t, %1; cvt.u32.u64 %0, t; }" : "=r"(a) : "l"(p));
    return a;
}
__device__ __forceinline__ void cp_async16(uint32_t dst, const void* src) {
    asm volatile("cp.async.cg.shared.global [%0], [%1], 16;" :: "r"(dst), "l"(src) : "memory");
}
__device__ __forceinline__ void cp_commit() {
    asm volatile("cp.async.commit_group;" ::: "memory");
}
template <int N> __device__ __forceinline__ void cp_wait() {
    asm volatile("cp.async.wait_group %0;" :: "n"(N) : "memory");
}
__device__ __forceinline__ void ldsm4(uint32_t addr, uint32_t* r) {
    asm volatile("ldmatrix.sync.aligned.m8n8.x4.shared.b16 {%0,%1,%2,%3}, [%4];"
                 : "=r"(r[0]), "=r"(r[1]), "=r"(r[2]), "=r"(r[3]) : "r"(addr));
}
// fp16 x fp16 -> fp32 accum
__device__ __forceinline__ void mma_f32(float* d, const uint32_t* a,
                                        uint32_t b0, uint32_t b1) {
    asm volatile(
        "mma.sync.aligned.m16n8k16.row.col.f32.f16.f16.f32 "
        "{%0,%1,%2,%3}, {%4,%5,%6,%7}, {%8,%9}, {%0,%1,%2,%3};"
        : "+f"(d[0]), "+f"(d[1]), "+f"(d[2]), "+f"(d[3])
        : "r"(a[0]), "r"(a[1]), "r"(a[2]), "r"(a[3]), "r"(b0), "r"(b1));
}
// fp16 x fp16 -> fp16 accum
__device__ __forceinline__ void mma_f16(uint32_t* d, const uint32_t* a,
                                        uint32_t b0, uint32_t b1) {
    asm volatile(
        "mma.sync.aligned.m16n8k16.row.col.f16.f16.f16.f16 "
        "{%0,%1}, {%2,%3,%4,%5}, {%6,%7}, {%0,%1};"
        : "+r"(d[0]), "+r"(d[1])
        : "r"(a[0]), "r"(a[1]), "r"(a[2]), "r"(a[3]), "r"(b0), "r"(b1));
}

// ---------------- prep: fp16 hi/lo splits + t3 + ls ----------------
__global__ void prep_kernel(const float* __restrict__ f, const float* __restrict__ s) {
    int i = blockIdx.x;
    int t = threadIdx.x;  // 128
    const float* fr = f + (size_t)i * D;
    const float* sr = s + (size_t)i * D;
    __half* Ar = g_Ah + (size_t)i * KD;
    __half* Br = g_Bh + (size_t)i * KD;
    float t3p = 0.f, lsp = 0.f;
    for (int d = t; d < D; d += 128) {
        float x = fr[d], sg = sr[d];
        float inv = 1.0f / sg;
        float a1 = x * x, a2 = x, b1 = inv, b2 = -2.0f * x * inv;
        __half h;
        h = __float2half_rn(a1); Ar[d]       = h; Ar[1024 + d] = __float2half_rn(a1 - __half2float(h));
        h = __float2half_rn(a2); Ar[512 + d] = h; Ar[1536 + d] = __float2half_rn(a2 - __half2float(h));
        h = __float2half_rn(b1); Br[d]       = h; Br[1024 + d] = __float2half_rn(b1 - __half2float(h));
        h = __float2half_rn(b2); Br[512 + d] = h; Br[1536 + d] = __float2half_rn(b2 - __half2float(h));
        t3p += a1 * inv;
        lsp += __logf(sg);
    }
    __shared__ float sh1[128], sh2[128];
    sh1[t] = t3p; sh2[t] = lsp;
    __syncthreads();
    for (int st = 64; st > 0; st >>= 1) {
        if (t < st) { sh1[t] += sh1[t + st]; sh2[t] += sh2[t + st]; }
        __syncthreads();
    }
    if (t == 0) { g_t3[i] = sh1[0]; g_ls[i] = sh2[0]; g_rowsum[i] = 0.f; }
}

// ---------------- gt + per-row/col constants ----------------
__global__ void gt_kernel(const float* __restrict__ f, const float* __restrict__ s,
                          const int* __restrict__ label) {
    int i = blockIdx.x;
    int lab = label[i];
    int pos = lab + (lab >= i ? 1 : 0);
    const float* xi = f + (size_t)i * D;
    const float* xp = f + (size_t)pos * D;
    const float* sp = s + (size_t)pos * D;
    float p = 0.f;
    for (int d = threadIdx.x; d < D; d += 256) {
        float dd = xi[d] - xp[d];
        p += dd * dd / sp[d];
    }
    __shared__ float sh[256];
    sh[threadIdx.x] = p;
    __syncthreads();
    for (int st = 128; st > 0; st >>= 1) {
        if (threadIdx.x < st) sh[threadIdx.x] += sh[threadIdx.x + st];
        __syncthreads();
    }
    if (threadIdx.x == 0) {
        g_c[i]  = 0.1f * sh[0] + 0.5f * g_ls[i];
        g_cj[i] = -0.5f * g_ls[pos] - 0.1f * g_t3[i];
    }
}

// ---------------- chunk loader (BK=128) ----------------
// chunks 0..15: cross — A col c*128 over [hi|lo], B col +1024 mod 2048 ([lo|hi])
// chunks 16..23: hihi — A,B cols (c-16)*128 in [0,1024)
__device__ __forceinline__ void load_chunk(int c, int st, int i0, int j0, uint32_t sb) {
    int acol, bcol;
    if (c < 16) { acol = c * 128; bcol = (acol + 1024) & 2047; }
    else        { acol = (c - 16) * 128; bcol = acol; }
    const uint32_t aS = sb + st * STAGE_SZ;
    const uint32_t bS = aS + A_SZ;
    const int tid = threadIdx.x;
#pragma unroll
    for (int it = 0; it < 16; it++) {           // A: 4096 16B segs
        int id = tid + it * 256;
        int row = id >> 4, kc = id & 15;
        cp_async16(aS + row * ROWB + kc * 16,
                   g_Ah + (size_t)(i0 + row) * KD + acol + kc * 8);
    }
#pragma unroll
    for (int it = 0; it < 8; it++) {            // B: 2048 16B segs
        int id = tid + it * 256;
        int row = id >> 4, kc = id & 15;
        cp_async16(bS + row * ROWB + kc * 16,
                   g_Bh + (size_t)(j0 + row) * KD + bcol + kc * 8);
    }
}

// ---------------- main dist kernel ----------------
__global__ __launch_bounds__(256)
void dist_kernel(float* __restrict__ out, int write_logits) {
    extern __shared__ char smem[];
    const uint32_t sb = smem_u32(smem);
    const int tid  = threadIdx.x;
    const int lane = tid & 31;
    const int wid  = tid >> 5;
    const int wm   = wid & 3;
    const int wn   = wid >> 2;
    const int i0 = blockIdx.y * TM;
    const int j0 = blockIdx.x * TN;

    // prologue: chunk 0 -> stage 0
    load_chunk(0, 0, i0, j0, sb);
    cp_commit();

    const uint32_t aoff = (wm * 64 + (lane & 15)) * ROWB + (lane >> 4) * 16;
    const uint32_t boff = (wn * 64 + (lane & 15)) * ROWB + (lane >> 4) * 16;

    uint32_t afr[2][4][4], bfr[2][4][4];

    // ---------------- phase A: cross (chunks 0..15, fp16 accum) ----------------
    uint32_t acch[4][8][2];
#pragma unroll
    for (int mi = 0; mi < 4; mi++)
#pragma unroll
        for (int ni = 0; ni < 8; ni++) { acch[mi][ni][0] = 0u; acch[mi][ni][1] = 0u; }

    for (int c = 0; c < 16; c++) {
        cp_wait<0>();
        __syncthreads();
        load_chunk(c + 1, (c + 1) & 1, i0, j0, sb);   // c=15 -> chunk 16 (phase B)
        cp_commit();

        const uint32_t aS = sb + (c & 1) * STAGE_SZ;
        const uint32_t bS = aS + A_SZ;
#pragma unroll
        for (int mi = 0; mi < 4; mi++) ldsm4(aS + aoff + mi * (16 * ROWB), afr[0][mi]);
#pragma unroll
        for (int np = 0; np < 4; np++) ldsm4(bS + boff + np * (16 * ROWB), bfr[0][np]);
#pragma unroll
        for (int ks = 0; ks < 8; ks++) {
            const int cur = ks & 1, nxt = cur ^ 1;
            if (ks < 7) {
#pragma unroll
                for (int mi = 0; mi < 4; mi++)
                    ldsm4(aS + aoff + mi * (16 * ROWB) + (ks + 1) * 32, afr[nxt][mi]);
#pragma unroll
                for (int np = 0; np < 4; np++)
                    ldsm4(bS + boff + np * (16 * ROWB) + (ks + 1) * 32, bfr[nxt][np]);
            }
#pragma unroll
            for (int mi = 0; mi < 4; mi++)
#pragma unroll
                for (int ni = 0; ni < 8; ni++)
                    mma_f16(acch[mi][ni], afr[cur][mi],
                            bfr[cur][ni >> 1][ni & 1], bfr[cur][ni >> 1][(ni & 1) + 2]);
        }
    }

    // convert cross fp16 accumulators to fp32
    float acc[4][8][4];
#pragma unroll
    for (int mi = 0; mi < 4; mi++)
#pragma unroll
        for (int ni = 0; ni < 8; ni++) {
            __half2 h0 = *(__half2*)&acch[mi][ni][0];
            __half2 h1 = *(__half2*)&acch[mi][ni][1];
            acc[mi][ni][0] = __low2float(h0);
            acc[mi][ni][1] = __high2float(h0);
            acc[mi][ni][2] = __low2float(h1);
            acc[mi][ni][3] = __high2float(h1);
        }

    // ---------------- phase B: hihi (chunks 16..23, fp32 accum) ----------------
    for (int c = 16; c < NCH; c++) {
        cp_wait<0>();
        __syncthreads();
        if (c + 1 < NCH) { load_chunk(c + 1, (c + 1) & 1, i0, j0, sb); cp_commit(); }

        const uint32_t aS = sb + (c & 1) * STAGE_SZ;
        const uint32_t bS = aS + A_SZ;
#pragma unroll
        for (int mi = 0; mi < 4; mi++) ldsm4(aS + aoff + mi * (16 * ROWB), afr[0][mi]);
#pragma unroll
        for (int np = 0; np < 4; np++) ldsm4(bS + boff + np * (16 * ROWB), bfr[0][np]);
#pragma unroll
        for (int ks = 0; ks < 8; ks++) {
            const int cur = ks & 1, nxt = cur ^ 1;
            if (ks < 7) {
#pragma unroll
                for (int mi = 0; mi < 4; mi++)
                    ldsm4(aS + aoff + mi * (16 * ROWB) + (ks + 1) * 32, afr[nxt][mi]);
#pragma unroll
                for (int np = 0; np < 4; np++)
                    ldsm4(bS + boff + np * (16 * ROWB) + (ks + 1) * 32, bfr[nxt][np]);
            }
#pragma unroll
            for (int mi = 0; mi < 4; mi++)
#pragma unroll
                for (int ni = 0; ni < 8; ni++)
                    mma_f32(acc[mi][ni], afr[cur][mi],
                            bfr[cur][ni >> 1][ni & 1], bfr[cur][ni >> 1][(ni & 1) + 2]);
        }
    }

    // ---------------- epilogue ----------------
    float cv0[4], cv1[4];
#pragma unroll
    for (int mi = 0; mi < 4; mi++) {
        int r0 = i0 + wm * 64 + mi * 16 + (lane >> 2);
        cv0[mi] = g_c[r0];
        cv1[mi] = g_c[r0 + 8];
    }
    float cjv[8][2];
#pragma unroll
    for (int ni = 0; ni < 8; ni++) {
        int cb = j0 + wn * 64 + (ni >> 1) * 16 + (ni & 1) * 8 + (lane & 3) * 2;
        cjv[ni][0] = g_cj[cb];
        cjv[ni][1] = g_cj[cb + 1];
    }

#pragma unroll
    for (int mi = 0; mi < 4; mi++) {
        const int r0 = i0 + wm * 64 + mi * 16 + (lane >> 2);
        const int r1 = r0 + 8;
        float rs0 = 0.f, rs1 = 0.f;
#pragma unroll
        for (int ni = 0; ni < 8; ni++) {
            const int cb = j0 + wn * 64 + (ni >> 1) * 16 + (ni & 1) * 8 + (lane & 3) * 2;
            float e0 = __expf(cv0[mi] + cjv[ni][0] - 0.1f * acc[mi][ni][0]);
            float e1 = __expf(cv0[mi] + cjv[ni][1] - 0.1f * acc[mi][ni][1]);
            float e2 = __expf(cv1[mi] + cjv[ni][0] - 0.1f * acc[mi][ni][2]);
            float e3 = __expf(cv1[mi] + cjv[ni][1] - 0.1f * acc[mi][ni][3]);
            if (cb     == r0) e0 = 0.f;
            if (cb + 1 == r0) e1 = 0.f;
            if (cb     == r1) e2 = 0.f;
            if (cb + 1 == r1) e3 = 0.f;
            rs0 += e0 + e1;
            rs1 += e2 + e3;
            if (write_logits) {
                if (cb     != r0) out[(size_t)r0 * NM1 + cb     - (cb     > r0)] = e0;
                if (cb + 1 != r0) out[(size_t)r0 * NM1 + cb + 1 - (cb + 1 > r0)] = e1;
                if (cb     != r1) out[(size_t)r1 * NM1 + cb     - (cb     > r1)] = e2;
                if (cb + 1 != r1) out[(size_t)r1 * NM1 + cb + 1 - (cb + 1 > r1)] = e3;
            }
        }
        rs0 += __shfl_xor_sync(0xFFFFFFFFu, rs0, 1);
        rs0 += __shfl_xor_sync(0xFFFFFFFFu, rs0, 2);
        rs1 += __shfl_xor_sync(0xFFFFFFFFu, rs1, 1);
        rs1 += __shfl_xor_sync(0xFFFFFFFFu, rs1, 2);
        if ((lane & 3) == 0) {
            atomicAdd(&g_rowsum[r0], rs0);
            atomicAdd(&g_rowsum[r1], rs1);
        }
    }
}

// ---------------- loss = mean(log(rowsum)) ----------------
__global__ void loss_kernel(float* __restrict__ loss_out) {
    __shared__ float sh[1024];
    float p = 0.f;
    for (int i = threadIdx.x; i < B2; i += 1024) p += __logf(g_rowsum[i]);
    sh[threadIdx.x] = p;
    __syncthreads();
    for (int st = 512; st > 0; st >>= 1) {
        if (threadIdx.x < st) sh[threadIdx.x] += sh[threadIdx.x + st];
        __syncthreads();
    }
    if (threadIdx.x == 0) *loss_out = sh[0] / (float)B2;
}

// ---------------- launch ----------------
extern "C" void kernel_launch(void* const* d_in, const int* in_sizes, int n_in,
                              void* d_out, int out_size) {
    const float* f     = (const float*)d_in[0];
    const float* s     = (const float*)d_in[1];
    const int*   label = (const int*)d_in[2];

    float* outf = (float*)d_out;
    const long long LOGN = (long long)B2 * NM1;
    float* loss_out  = nullptr;
    float* logit_out = nullptr;
    if ((long long)out_size == LOGN + 1) { loss_out = outf; logit_out = outf + 1; }
    else if ((long long)out_size == LOGN) { logit_out = outf; }
    else { loss_out = outf; }

    cudaFuncSetAttribute(dist_kernel, cudaFuncAttributeMaxDynamicSharedMemorySize, SM_TOTAL);

    prep_kernel<<<B2, 128>>>(f, s);
    gt_kernel<<<B2, 256>>>(f, s, label);

    dim3 grid(B2 / TN, B2 / TM);
    dist_kernel<<<grid, 256, SM_TOTAL>>>(logit_out ? logit_out : outf,
                                         logit_out != nullptr ? 1 : 0);

    if (loss_out) loss_kernel<<<1, 1024>>>(loss_out);
}

// round 13
// speedup vs baseline: 1.0183x; 1.0183x over previous
#include <cuda_runtime.h>
#include <cuda_fp16.h>
#include <cstdint>

#define B2   8192
#define D    512
#define KD   2048      // fp16 cols: [0,1024) hi, [1024,2048) lo
#define NM1  8191

#define TM   256
#define TN   128
#define BK   64        // fp16 per chunk (128 B rows)
#define NSTG 3
#define NCH  48        // 32 cross (K=2048, fp16 acc) + 16 hihi (K=1024, fp32 acc)

#define ROWB 144                       // 128 B data + 16 B pad
#define A_SZ (256 * ROWB)              // 36864
#define B_SZ (128 * ROWB)              // 18432
#define STAGE_SZ (A_SZ + B_SZ)         // 55296
#define SM_TOTAL (NSTG * STAGE_SZ)     // 165888

// ---------------- device scratch ----------------
__device__ __align__(128) __half g_Ah[(size_t)B2 * KD];  // [hi(x^2)|hi(x)|lo(x^2)|lo(x)]
__device__ __align__(128) __half g_Bh[(size_t)B2 * KD];  // [hi(1/s)|hi(-2x/s)|lo(1/s)|lo(-2x/s)]
__device__ float g_t3[B2];
__device__ float g_ls[B2];
__device__ float g_c[B2];      // 0.1*gt_i + 0.5*ls_i
__device__ float g_cj[B2];     // -0.5*ls[pos(j)] - 0.1*t3[j]
__device__ float g_rowsum[B2];

// ---------------- PTX helpers ----------------
__device__ __forceinline__ uint32_t smem_u32(const void* p) {
    uint32_t a;
    asm("{ .reg .u64 t; cvta.to.shared.u64 t, %1; cvt.u32.u64 %0, t; }" : "=r"(a) : "l"(p));
    return a;
}
__device__ __forceinline__ void cp_async16(uint32_t dst, const void* src) {
    asm volatile("cp.async.cg.shared.global [%0], [%1], 16;" :: "r"(dst), "l"(src) : "memory");
}
__device__ __forceinline__ void cp_commit() {
    asm volatile("cp.async.commit_group;" ::: "memory");
}
template <int N> __device__ __forceinline__ void cp_wait() {
    asm volatile("cp.async.wait_group %0;" :: "n"(N) : "memory");
}
__device__ __forceinline__ void ldsm4(uint32_t addr, uint32_t* r) {
    asm volatile("ldmatrix.sync.aligned.m8n8.x4.shared.b16 {%0,%1,%2,%3}, [%4];"
                 : "=r"(r[0]), "=r"(r[1]), "=r"(r[2]), "=r"(r[3]) : "r"(addr));
}
// fp16 x fp16 -> fp32 accum
__device__ __forceinline__ void mma_f32(float* d, const uint32_t* a,
                                        uint32_t b0, uint32_t b1) {
    asm volatile(
        "mma.sync.aligned.m16n8k16.row.col.f32.f16.f16.f32 "
        "{%0,%1,%2,%3}, {%4,%5,%6,%7}, {%8,%9}, {%0,%1,%2,%3};"
        : "+f"(d[0]), "+f"(d[1]), "+f"(d[2]), "+f"(d[3])
        : "r"(a[0]), "r"(a[1]), "r"(a[2]), "r"(a[3]), "r"(b0), "r"(b1));
}
// fp16 x fp16 -> fp16 accum
__device__ __forceinline__ void mma_f16(uint32_t* d, const uint32_t* a,
                                        uint32_t b0, uint32_t b1) {
    asm volatile(
        "mma.sync.aligned.m16n8k16.row.col.f16.f16.f16.f16 "
        "{%0,%1}, {%2,%3,%4,%5}, {%6,%7}, {%0,%1};"
        : "+r"(d[0]), "+r"(d[1])
        : "r"(a[0]), "r"(a[1]), "r"(a[2]), "r"(a[3]), "r"(b0), "r"(b1));
}

// ---------------- prep: fp16 hi/lo splits + t3 + ls ----------------
__global__ void prep_kernel(const float* __restrict__ f, const float* __restrict__ s) {
    int i = blockIdx.x;
    int t = threadIdx.x;  // 128
    const float* fr = f + (size_t)i * D;
    const float* sr = s + (size_t)i * D;
    __half* Ar = g_Ah + (size_t)i * KD;
    __half* Br = g_Bh + (size_t)i * KD;
    float t3p = 0.f, lsp = 0.f;
    for (int d = t; d < D; d += 128) {
        float x = fr[d], sg = sr[d];
        float inv = 1.0f / sg;
        float a1 = x * x, a2 = x, b1 = inv, b2 = -2.0f * x * inv;
        __half h;
        h = __float2half_rn(a1); Ar[d]       = h; Ar[1024 + d] = __float2half_rn(a1 - __half2float(h));
        h = __float2half_rn(a2); Ar[512 + d] = h; Ar[1536 + d] = __float2half_rn(a2 - __half2float(h));
        h = __float2half_rn(b1); Br[d]       = h; Br[1024 + d] = __float2half_rn(b1 - __half2float(h));
        h = __float2half_rn(b2); Br[512 + d] = h; Br[1536 + d] = __float2half_rn(b2 - __half2float(h));
        t3p += a1 * inv;
        lsp += __logf(sg);
    }
    __shared__ float sh1[128], sh2[128];
    sh1[t] = t3p; sh2[t] = lsp;
    __syncthreads();
    for (int st = 64; st > 0; st >>= 1) {
        if (t < st) { sh1[t] += sh1[t + st]; sh2[t] += sh2[t + st]; }
        __syncthreads();
    }
    if (t == 0) { g_t3[i] = sh1[0]; g_ls[i] = sh2[0]; g_rowsum[i] = 0.f; }
}

// ---------------- gt + per-row/col constants ----------------
__global__ void gt_kernel(const float* __restrict__ f, const float* __restrict__ s,
                          const int* __restrict__ label) {
    int i = blockIdx.x;
    int lab = label[i];
    int pos = lab + (lab >= i ? 1 : 0);
    const float* xi = f + (size_t)i * D;
    const float* xp = f + (size_t)pos * D;
    const float* sp = s + (size_t)pos * D;
    float p = 0.f;
    for (int d = threadIdx.x; d < D; d += 256) {
        float dd = xi[d] - xp[d];
        p += dd * dd / sp[d];
    }
    __shared__ float sh[256];
    sh[threadIdx.x] = p;
    __syncthreads();
    for (int st = 128; st > 0; st >>= 1) {
        if (threadIdx.x < st) sh[threadIdx.x] += sh[threadIdx.x + st];
        __syncthreads();
    }
    if (threadIdx.x == 0) {
        g_c[i]  = 0.1f * sh[0] + 0.5f * g_ls[i];
        g_cj[i] = -0.5f * g_ls[pos] - 0.1f * g_t3[i];
    }
}

// ---------------- chunk loader (BK=64) ----------------
// chunks 0..31:  cross — A col c*64 over [hi|lo], B col +1024 mod 2048 ([lo|hi])
// chunks 32..47: hihi  — A,B cols (c-32)*64 in [0,1024)
__device__ __forceinline__ void load_chunk(int c, int st, int i0, int j0, uint32_t sb) {
    int acol, bcol;
    if (c < 32) { acol = c * 64; bcol = (acol + 1024) & 2047; }
    else        { acol = (c - 32) * 64; bcol = acol; }
    const uint32_t aS = sb + st * STAGE_SZ;
    const uint32_t bS = aS + A_SZ;
    const int tid = threadIdx.x;
#pragma unroll
    for (int it = 0; it < 8; it++) {            // A: 2048 16B segs
        int id = tid + it * 256;
        int row = id >> 3, kc = id & 7;
        cp_async16(aS + row * ROWB + kc * 16,
                   g_Ah + (size_t)(i0 + row) * KD + acol + kc * 8);
    }
#pragma unroll
    for (int it = 0; it < 4; it++) {            // B: 1024 16B segs
        int id = tid + it * 256;
        int row = id >> 3, kc = id & 7;
        cp_async16(bS + row * ROWB + kc * 16,
                   g_Bh + (size_t)(j0 + row) * KD + bcol + kc * 8);
    }
}

// ---------------- main dist kernel: fp16-acc cross + fp32-acc hihi ----------
__global__ __launch_bounds__(256)
void dist_kernel(float* __restrict__ out, int write_logits) {
    extern __shared__ char smem[];
    const uint32_t sb = smem_u32(smem);
    const int tid  = threadIdx.x;
    const int lane = tid & 31;
    const int wid  = tid >> 5;
    const int wm   = wid & 3;
    const int wn   = wid >> 2;
    const int i0 = blockIdx.y * TM;
    const int j0 = blockIdx.x * TN;

    // prologue: stages 0,1
#pragma unroll
    for (int s = 0; s < NSTG - 1; s++) { load_chunk(s, s, i0, j0, sb); cp_commit(); }

    const uint32_t aoff = (wm * 64 + (lane & 15)) * ROWB + (lane >> 4) * 16;
    const uint32_t boff = (wn * 64 + (lane & 15)) * ROWB + (lane >> 4) * 16;

    uint32_t afr[2][4][4], bfr[2][4][4];

    // ---------------- phase A: cross (chunks 0..31, fp16 accum) ----------------
    uint32_t acch[4][8][2];
#pragma unroll
    for (int mi = 0; mi < 4; mi++)
#pragma unroll
        for (int ni = 0; ni < 8; ni++) { acch[mi][ni][0] = 0u; acch[mi][ni][1] = 0u; }

    for (int c = 0; c < 32; c++) {
        cp_wait<1>();
        __syncthreads();
        int pf = c + NSTG - 1;
        load_chunk(pf, pf % NSTG, i0, j0, sb);
        cp_commit();

        const uint32_t aS = sb + (c % NSTG) * STAGE_SZ;
        const uint32_t bS = aS + A_SZ;
#pragma unroll
        for (int mi = 0; mi < 4; mi++) ldsm4(aS + aoff + mi * (16 * ROWB), afr[0][mi]);
#pragma unroll
        for (int np = 0; np < 4; np++) ldsm4(bS + boff + np * (16 * ROWB), bfr[0][np]);
#pragma unroll
        for (int ks = 0; ks < 4; ks++) {
            const int cur = ks & 1, nxt = cur ^ 1;
            if (ks < 3) {
#pragma unroll
                for (int mi = 0; mi < 4; mi++)
                    ldsm4(aS + aoff + mi * (16 * ROWB) + (ks + 1) * 32, afr[nxt][mi]);
#pragma unroll
                for (int np = 0; np < 4; np++)
                    ldsm4(bS + boff + np * (16 * ROWB) + (ks + 1) * 32, bfr[nxt][np]);
            }
#pragma unroll
            for (int mi = 0; mi < 4; mi++)
#pragma unroll
                for (int ni = 0; ni < 8; ni++)
                    mma_f16(acch[mi][ni], afr[cur][mi],
                            bfr[cur][ni >> 1][ni & 1], bfr[cur][ni >> 1][(ni & 1) + 2]);
        }
    }

    // convert cross fp16 accumulators to fp32
    float acc[4][8][4];
#pragma unroll
    for (int mi = 0; mi < 4; mi++)
#pragma unroll
        for (int ni = 0; ni < 8; ni++) {
            __half2 h0 = *(__half2*)&acch[mi][ni][0];
            __half2 h1 = *(__half2*)&acch[mi][ni][1];
            acc[mi][ni][0] = __low2float(h0);
            acc[mi][ni][1] = __high2float(h0);
            acc[mi][ni][2] = __low2float(h1);
            acc[mi][ni][3] = __high2float(h1);
        }

    // ---------------- phase B: hihi (chunks 32..47, fp32 accum) ----------------
    for (int c = 32; c < NCH; c++) {
        cp_wait<1>();
        __syncthreads();
        int pf = c + NSTG - 1;
        if (pf < NCH) { load_chunk(pf, pf % NSTG, i0, j0, sb); cp_commit(); }

        const uint32_t aS = sb + (c % NSTG) * STAGE_SZ;
        const uint32_t bS = aS + A_SZ;
#pragma unroll
        for (int mi = 0; mi < 4; mi++) ldsm4(aS + aoff + mi * (16 * ROWB), afr[0][mi]);
#pragma unroll
        for (int np = 0; np < 4; np++) ldsm4(bS + boff + np * (16 * ROWB), bfr[0][np]);
#pragma unroll
        for (int ks = 0; ks < 4; ks++) {
            const int cur = ks & 1, nxt = cur ^ 1;
            if (ks < 3) {
#pragma unroll
                for (int mi = 0; mi < 4; mi++)
                    ldsm4(aS + aoff + mi * (16 * ROWB) + (ks + 1) * 32, afr[nxt][mi]);
#pragma unroll
                for (int np = 0; np < 4; np++)
                    ldsm4(bS + boff + np * (16 * ROWB) + (ks + 1) * 32, bfr[nxt][np]);
            }
#pragma unroll
            for (int mi = 0; mi < 4; mi++)
#pragma unroll
                for (int ni = 0; ni < 8; ni++)
                    mma_f32(acc[mi][ni], afr[cur][mi],
                            bfr[cur][ni >> 1][ni & 1], bfr[cur][ni >> 1][(ni & 1) + 2]);
        }
    }

    // ---------------- epilogue ----------------
    float cv0[4], cv1[4];
#pragma unroll
    for (int mi = 0; mi < 4; mi++) {
        int r0 = i0 + wm * 64 + mi * 16 + (lane >> 2);
        cv0[mi] = g_c[r0];
        cv1[mi] = g_c[r0 + 8];
    }
    float cjv[8][2];
#pragma unroll
    for (int ni = 0; ni < 8; ni++) {
        int cb = j0 + wn * 64 + (ni >> 1) * 16 + (ni & 1) * 8 + (lane & 3) * 2;
        cjv[ni][0] = g_cj[cb];
        cjv[ni][1] = g_cj[cb + 1];
    }

#pragma unroll
    for (int mi = 0; mi < 4; mi++) {
        const int r0 = i0 + wm * 64 + mi * 16 + (lane >> 2);
        const int r1 = r0 + 8;
        float rs0 = 0.f, rs1 = 0.f;
#pragma unroll
        for (int ni = 0; ni < 8; ni++) {
            const int cb = j0 + wn * 64 + (ni >> 1) * 16 + (ni & 1) * 8 + (lane & 3) * 2;
            float e0 = __expf(cv0[mi] + cjv[ni][0] - 0.1f * acc[mi][ni][0]);
            float e1 = __expf(cv0[mi] + cjv[ni][1] - 0.1f * acc[mi][ni][1]);
            float e2 = __expf(cv1[mi] + cjv[ni][0] - 0.1f * acc[mi][ni][2]);
            float e3 = __expf(cv1[mi] + cjv[ni][1] - 0.1f * acc[mi][ni][3]);
            if (cb     == r0) e0 = 0.f;
            if (cb + 1 == r0) e1 = 0.f;
            if (cb     == r1) e2 = 0.f;
            if (cb + 1 == r1) e3 = 0.f;
            rs0 += e0 + e1;
            rs1 += e2 + e3;
            if (write_logits) {
                if (cb     != r0) out[(size_t)r0 * NM1 + cb     - (cb     > r0)] = e0;
                if (cb + 1 != r0) out[(size_t)r0 * NM1 + cb + 1 - (cb + 1 > r0)] = e1;
                if (cb     != r1) out[(size_t)r1 * NM1 + cb     - (cb     > r1)] = e2;
                if (cb + 1 != r1) out[(size_t)r1 * NM1 + cb + 1 - (cb + 1 > r1)] = e3;
            }
        }
        rs0 += __shfl_xor_sync(0xFFFFFFFFu, rs0, 1);
        rs0 += __shfl_xor_sync(0xFFFFFFFFu, rs0, 2);
        rs1 += __shfl_xor_sync(0xFFFFFFFFu, rs1, 1);
        rs1 += __shfl_xor_sync(0xFFFFFFFFu, rs1, 2);
        if ((lane & 3) == 0) {
            atomicAdd(&g_rowsum[r0], rs0);
            atomicAdd(&g_rowsum[r1], rs1);
        }
    }
}

// ---------------- loss = mean(log(rowsum)) ----------------
__global__ void loss_kernel(float* __restrict__ loss_out) {
    __shared__ float sh[1024];
    float p = 0.f;
    for (int i = threadIdx.x; i < B2; i += 1024) p += __logf(g_rowsum[i]);
    sh[threadIdx.x] = p;
    __syncthreads();
    for (int st = 512; st > 0; st >>= 1) {
        if (threadIdx.x < st) sh[threadIdx.x] += sh[threadIdx.x + st];
        __syncthreads();
    }
    if (threadIdx.x == 0) *loss_out = sh[0] / (float)B2;
}

// ---------------- launch ----------------
extern "C" void kernel_launch(void* const* d_in, const int* in_sizes, int n_in,
                              void* d_out, int out_size) {
    const float* f     = (const float*)d_in[0];
    const float* s     = (const float*)d_in[1];
    const int*   label = (const int*)d_in[2];

    float* outf = (float*)d_out;
    const long long LOGN = (long long)B2 * NM1;
    float* loss_out  = nullptr;
    float* logit_out = nullptr;
    if ((long long)out_size == LOGN + 1) { loss_out = outf; logit_out = outf + 1; }
    else if ((long long)out_size == LOGN) { logit_out = outf; }
    else { loss_out = outf; }

    cudaFuncSetAttribute(dist_kernel, cudaFuncAttributeMaxDynamicSharedMemorySize, SM_TOTAL);

    prep_kernel<<<B2, 128>>>(f, s);
    gt_kernel<<<B2, 256>>>(f, s, label);

    dim3 grid(B2 / TN, B2 / TM);
    dist_kernel<<<grid, 256, SM_TOTAL>>>(logit_out ? logit_out : outf,
                                         logit_out != nullptr ? 1 : 0);

    if (loss_out) loss_kernel<<<1, 1024>>>(loss_out);
}